// round 14
// baseline (speedup 1.0000x reference)
#include <cuda_runtime.h>
#include <math.h>

#define B_ 32
#define C_ 256
#define H_ 56
#define W_ 56
#define HW_ (H_*W_)          // 3136
#define R_ 16
#define HW4_ (HW_/4)         // 784
#define HW8_ (HW_/8)         // 392 float8 per plane
#define QF8_ 98              // f8 stride for 4-per-thread final (392/4)
#define CG_ 32               // channels per group
#define NCG_ 8               // channel groups

// Scratch — 32B aligned
__device__ __align__(32) float g_avg[B_*C_];
__device__ __align__(32) float g_max[B_*C_];
__device__ __align__(32) float g_ca [B_*C_];
__device__ __align__(32) float g_ps [B_*NCG_*HW_];
__device__ __align__(32) float g_pm [B_*NCG_*HW_];
__device__ __align__(32) float g_sa [B_*HW_];

// ---- 32-byte loads ----------------------------------------------------------
__device__ __forceinline__ void ldg8(const float* p, float4& lo, float4& hi) {
    unsigned long long r0, r1, r2, r3;
    asm volatile("ld.global.nc.v4.b64 {%0,%1,%2,%3}, [%4];"
                 : "=l"(r0), "=l"(r1), "=l"(r2), "=l"(r3) : "l"(p));
    lo.x = __uint_as_float((unsigned)r0); lo.y = __uint_as_float((unsigned)(r0 >> 32));
    lo.z = __uint_as_float((unsigned)r1); lo.w = __uint_as_float((unsigned)(r1 >> 32));
    hi.x = __uint_as_float((unsigned)r2); hi.y = __uint_as_float((unsigned)(r2 >> 32));
    hi.z = __uint_as_float((unsigned)r3); hi.w = __uint_as_float((unsigned)(r3 >> 32));
}
__device__ __forceinline__ void ldg_evl8(const float* p, float4& lo, float4& hi) {
    unsigned long long r0, r1, r2, r3;
    asm volatile("ld.global.nc.L2::evict_last.v4.b64 {%0,%1,%2,%3}, [%4];"
                 : "=l"(r0), "=l"(r1), "=l"(r2), "=l"(r3) : "l"(p));
    lo.x = __uint_as_float((unsigned)r0); lo.y = __uint_as_float((unsigned)(r0 >> 32));
    lo.z = __uint_as_float((unsigned)r1); lo.w = __uint_as_float((unsigned)(r1 >> 32));
    hi.x = __uint_as_float((unsigned)r2); hi.y = __uint_as_float((unsigned)(r2 >> 32));
    hi.z = __uint_as_float((unsigned)r3); hi.w = __uint_as_float((unsigned)(r3 >> 32));
}
__device__ __forceinline__ void ldg_evf8(const float* p, float4& lo, float4& hi) {
    unsigned long long r0, r1, r2, r3;
    asm volatile("ld.global.nc.L2::evict_first.v4.b64 {%0,%1,%2,%3}, [%4];"
                 : "=l"(r0), "=l"(r1), "=l"(r2), "=l"(r3) : "l"(p));
    lo.x = __uint_as_float((unsigned)r0); lo.y = __uint_as_float((unsigned)(r0 >> 32));
    lo.z = __uint_as_float((unsigned)r1); lo.w = __uint_as_float((unsigned)(r1 >> 32));
    hi.x = __uint_as_float((unsigned)r2); hi.y = __uint_as_float((unsigned)(r2 >> 32));
    hi.z = __uint_as_float((unsigned)r3); hi.w = __uint_as_float((unsigned)(r3 >> 32));
}

// ---------------------------------------------------------------------------
// Kernel 1: per-(b,c) spatial mean & max. One warp per plane, 32B loads.
// ---------------------------------------------------------------------------
__global__ __launch_bounds__(256) void k_spatial_pool(const float* __restrict__ x) {
    const int warp = threadIdx.x >> 5, lane = threadIdx.x & 31;
    const int bc = blockIdx.x * 8 + warp;
    const float* __restrict__ xp = x + (size_t)bc * HW_;
    float s = 0.f, m = -INFINITY;
    #pragma unroll
    for (int batch = 0; batch < 2; batch++) {
        float4 lo[6], hi[6];
        #pragma unroll
        for (int j = 0; j < 6; j++)
            ldg_evl8(xp + (size_t)(lane + 32 * (batch * 6 + j)) * 8, lo[j], hi[j]);
        #pragma unroll
        for (int j = 0; j < 6; j++) {
            s += ((lo[j].x + lo[j].y) + (lo[j].z + lo[j].w))
               + ((hi[j].x + hi[j].y) + (hi[j].z + hi[j].w));
            float m1 = fmaxf(fmaxf(lo[j].x, lo[j].y), fmaxf(lo[j].z, lo[j].w));
            float m2 = fmaxf(fmaxf(hi[j].x, hi[j].y), fmaxf(hi[j].z, hi[j].w));
            m = fmaxf(m, fmaxf(m1, m2));
        }
    }
    if (lane < 8) {
        float4 lo, hi;
        ldg_evl8(xp + (size_t)(384 + lane) * 8, lo, hi);
        s += ((lo.x + lo.y) + (lo.z + lo.w)) + ((hi.x + hi.y) + (hi.z + hi.w));
        float m1 = fmaxf(fmaxf(lo.x, lo.y), fmaxf(lo.z, lo.w));
        float m2 = fmaxf(fmaxf(hi.x, hi.y), fmaxf(hi.z, hi.w));
        m = fmaxf(m, fmaxf(m1, m2));
    }
    #pragma unroll
    for (int o = 16; o > 0; o >>= 1) {
        s += __shfl_xor_sync(0xffffffffu, s, o);
        m = fmaxf(m, __shfl_xor_sync(0xffffffffu, m, o));
    }
    if (lane == 0) {
        g_avg[bc] = s * (1.0f / HW_);
        g_max[bc] = m;
    }
}

// ---------------------------------------------------------------------------
// Kernel 1b: channel-attention MLP, one block per batch -> g_ca.
// ---------------------------------------------------------------------------
__global__ __launch_bounds__(256) void k_mlp(const float* __restrict__ w1,
                                             const float* __restrict__ w2) {
    const int b = blockIdx.x;
    const int t = threadIdx.x;
    __shared__ float sva[C_], svm[C_], hs[R_];
    sva[t] = g_avg[b * C_ + t];
    svm[t] = g_max[b * C_ + t];
    __syncthreads();
    {
        const int r = t >> 4, j = t & 15;
        const float* __restrict__ wr = w1 + r * C_ + j * 16;
        const float* __restrict__ va = sva + j * 16;
        const float* __restrict__ vm = svm + j * 16;
        float pa = 0.f, pmx = 0.f;
        #pragma unroll
        for (int i = 0; i < 16; i++) {
            pa  = fmaf(wr[i], va[i], pa);
            pmx = fmaf(wr[i], vm[i], pmx);
        }
        #pragma unroll
        for (int o = 8; o > 0; o >>= 1) {
            pa  += __shfl_down_sync(0xffffffffu, pa,  o, 16);
            pmx += __shfl_down_sync(0xffffffffu, pmx, o, 16);
        }
        if (j == 0) hs[r] = fmaxf(pa, 0.f) + fmaxf(pmx, 0.f);
    }
    __syncthreads();
    float o = 0.f;
    const float* __restrict__ w2r = w2 + t * R_;
    #pragma unroll
    for (int r = 0; r < R_; r++) o = fmaf(w2r[r], hs[r], o);
    g_ca[b * C_ + t] = 1.0f / (1.0f + __expf(-o));
}

// ---------------------------------------------------------------------------
// Kernel 2: partial channel mean/max of x*ca. One block per (cg, b):
// grid (8, 32) = 256 blocks x 416 threads; threads 0..391 own one f8 each.
// ---------------------------------------------------------------------------
__global__ __launch_bounds__(416, 2) void k_chan_pool(const float* __restrict__ x) {
    const int cg = blockIdx.x, b = blockIdx.y;
    const int t = threadIdx.x;
    __shared__ float sca[C_];
    if (t < C_) sca[t] = g_ca[b * C_ + t];
    __syncthreads();

    const int f8 = t;
    if (f8 >= HW8_) return;
    const float* __restrict__ xb =
        x + (size_t)b * C_ * HW_ + (size_t)cg * CG_ * HW_ + (size_t)f8 * 8;
    const float* __restrict__ scg = sca + cg * CG_;
    float4 slo = make_float4(0.f, 0.f, 0.f, 0.f), shi = slo;
    float4 mlo = make_float4(-INFINITY, -INFINITY, -INFINITY, -INFINITY), mhi = mlo;
    #pragma unroll
    for (int batch = 0; batch < 4; batch++) {
        float4 lo[8], hi[8];
        #pragma unroll
        for (int j = 0; j < 8; j++)
            ldg_evl8(xb + (size_t)(batch * 8 + j) * HW_, lo[j], hi[j]);
        #pragma unroll
        for (int j = 0; j < 8; j++) {
            const float a = scg[batch * 8 + j];
            float v0 = lo[j].x * a, v1 = lo[j].y * a, v2 = lo[j].z * a, v3 = lo[j].w * a;
            float v4 = hi[j].x * a, v5 = hi[j].y * a, v6 = hi[j].z * a, v7 = hi[j].w * a;
            slo.x += v0; slo.y += v1; slo.z += v2; slo.w += v3;
            shi.x += v4; shi.y += v5; shi.z += v6; shi.w += v7;
            mlo.x = fmaxf(mlo.x, v0); mlo.y = fmaxf(mlo.y, v1);
            mlo.z = fmaxf(mlo.z, v2); mlo.w = fmaxf(mlo.w, v3);
            mhi.x = fmaxf(mhi.x, v4); mhi.y = fmaxf(mhi.y, v5);
            mhi.z = fmaxf(mhi.z, v6); mhi.w = fmaxf(mhi.w, v7);
        }
    }
    const size_t base = ((size_t)b * NCG_ + cg) * HW_;
    float4* __restrict__ pav = (float4*)(g_ps + base);
    float4* __restrict__ pmx = (float4*)(g_pm + base);
    pav[f8 * 2]     = slo;
    pav[f8 * 2 + 1] = shi;
    pmx[f8 * 2]     = mlo;
    pmx[f8 * 2 + 1] = mhi;
}

// ---------------------------------------------------------------------------
// Kernel 3: merge partials + 7x7 conv + sigmoid -> g_sa.
// TR=8: grid (7, 32) = 224 blocks x 256 threads.
// Merge split across warps: threads 0..97 sum-merge g_ps; threads 128..225
// max-merge g_pm. One batch of 8 front-batched 32B loads per thread.
// ---------------------------------------------------------------------------
#define TR 8
#define HR (TR + 6)                // 14 halo rows
#define HF8 (HR * W_ / 8)          // 98 float8 in halo tile
#define W8_ (W_ / 8)               // 7 f8 per row

__global__ __launch_bounds__(256) void k_sa(const float* __restrict__ wsp) {
    const int b  = blockIdx.y;
    const int h0 = blockIdx.x * TR;
    const int t  = threadIdx.x;

    __shared__ float sw[98];
    __shared__ __align__(32) float spa[HR * W_];
    __shared__ __align__(32) float spm[HR * W_];

    if (t < 98) sw[t] = wsp[t];

    const int half = t >> 7;           // 0 => ps(sum), 1 => pm(max)
    const int idx  = t & 127;          // halo f8 index within half
    if (idx < HF8) {
        const int r  = idx / W8_;      // halo row 0..13
        const int c8 = idx - r * W8_;  // f8 column 0..6
        const int hh = h0 - 3 + r;
        float4 alo = make_float4(0.f, 0.f, 0.f, 0.f), ahi = alo;
        if (hh >= 0 && hh < H_) {
            const size_t p = (size_t)(hh * W8_ + c8) * 8;
            const float* __restrict__ src =
                (half ? g_pm : g_ps) + (size_t)b * NCG_ * HW_ + p;
            float4 lo[NCG_], hi[NCG_];
            #pragma unroll
            for (int g = 0; g < NCG_; g++) ldg8(src + (size_t)g * HW_, lo[g], hi[g]);
            alo = lo[0]; ahi = hi[0];
            if (half == 0) {
                #pragma unroll
                for (int g = 1; g < NCG_; g++) {
                    alo.x += lo[g].x; alo.y += lo[g].y; alo.z += lo[g].z; alo.w += lo[g].w;
                    ahi.x += hi[g].x; ahi.y += hi[g].y; ahi.z += hi[g].z; ahi.w += hi[g].w;
                }
                const float inv = 1.0f / C_;
                alo.x *= inv; alo.y *= inv; alo.z *= inv; alo.w *= inv;
                ahi.x *= inv; ahi.y *= inv; ahi.z *= inv; ahi.w *= inv;
            } else {
                #pragma unroll
                for (int g = 1; g < NCG_; g++) {
                    alo.x = fmaxf(alo.x, lo[g].x); alo.y = fmaxf(alo.y, lo[g].y);
                    alo.z = fmaxf(alo.z, lo[g].z); alo.w = fmaxf(alo.w, lo[g].w);
                    ahi.x = fmaxf(ahi.x, hi[g].x); ahi.y = fmaxf(ahi.y, hi[g].y);
                    ahi.z = fmaxf(ahi.z, hi[g].z); ahi.w = fmaxf(ahi.w, hi[g].w);
                }
            }
        }
        float* dst = half ? spm : spa;
        ((float4*)dst)[idx * 2]     = alo;
        ((float4*)dst)[idx * 2 + 1] = ahi;
    }
    __syncthreads();

    for (int p = t; p < TR * W_; p += 256) {
        const int hr = p / W_;
        const int wd = p - hr * W_;
        const int h  = h0 + hr;
        float acc = 0.f;
        #pragma unroll
        for (int kh = 0; kh < 7; kh++) {
            const int hh = h + kh - 3;
            if (hh < 0 || hh >= H_) continue;
            const int sr = hh - (h0 - 3);   // 0..13
            #pragma unroll
            for (int kw = 0; kw < 7; kw++) {
                const int ww = wd + kw - 3;
                if (ww < 0 || ww >= W_) continue;
                acc = fmaf(sw[kh * 7 + kw],      spa[sr * W_ + ww], acc);
                acc = fmaf(sw[49 + kh * 7 + kw], spm[sr * W_ + ww], acc);
            }
        }
        g_sa[b * HW_ + h * W_ + wd] = 1.0f / (1.0f + __expf(-acc));
    }
}

// ---------------------------------------------------------------------------
// Kernel 4: out = x * (1 + ca*sa). 4 f8 per thread (stride 98 f8 in-plane).
// ---------------------------------------------------------------------------
__global__ __launch_bounds__(256) void k_final(const float* __restrict__ x,
                                               float* __restrict__ out) {
    const int g = blockIdx.x * 256 + threadIdx.x;
    const int plane = g / QF8_;
    const int r = g - plane * QF8_;
    const int b = plane >> 8;
    const float ca = __ldg(&g_ca[plane]);
    const float*  __restrict__ xs = x + (size_t)plane * HW_ + (size_t)r * 8;
    const float4* __restrict__ ss = (const float4*)(g_sa + (size_t)b * HW_) + r * 2;
    float4*       __restrict__ os = (float4*)(out + (size_t)plane * HW_) + r * 2;

    float4 vlo[4], vhi[4], slo[4], shi[4];
    #pragma unroll
    for (int j = 0; j < 4; j++)
        ldg_evf8(xs + (size_t)j * QF8_ * 8, vlo[j], vhi[j]);
    #pragma unroll
    for (int j = 0; j < 4; j++) {
        slo[j] = __ldg(ss + j * QF8_ * 2);
        shi[j] = __ldg(ss + j * QF8_ * 2 + 1);
    }
    #pragma unroll
    for (int j = 0; j < 4; j++) {
        float4 o1, o2;
        o1.x = vlo[j].x * fmaf(ca, slo[j].x, 1.0f);
        o1.y = vlo[j].y * fmaf(ca, slo[j].y, 1.0f);
        o1.z = vlo[j].z * fmaf(ca, slo[j].z, 1.0f);
        o1.w = vlo[j].w * fmaf(ca, slo[j].w, 1.0f);
        o2.x = vhi[j].x * fmaf(ca, shi[j].x, 1.0f);
        o2.y = vhi[j].y * fmaf(ca, shi[j].y, 1.0f);
        o2.z = vhi[j].z * fmaf(ca, shi[j].z, 1.0f);
        o2.w = vhi[j].w * fmaf(ca, shi[j].w, 1.0f);
        os[j * QF8_ * 2]     = o1;
        os[j * QF8_ * 2 + 1] = o2;
    }
}

// ---------------------------------------------------------------------------
extern "C" void kernel_launch(void* const* d_in, const int* in_sizes, int n_in,
                              void* d_out, int out_size) {
    const float* x   = (const float*)d_in[0];
    const float* w1  = (const float*)d_in[1];
    const float* w2  = (const float*)d_in[2];
    const float* wsp = (const float*)d_in[3];
    float* out = (float*)d_out;

    k_spatial_pool<<<1024, 256>>>(x);
    k_mlp<<<B_, 256>>>(w1, w2);
    dim3 g2(NCG_, B_);                           // (8, 32) = 256 blocks
    k_chan_pool<<<g2, 416>>>(x);
    dim3 g3(H_ / TR, B_);                        // (7, 32) = 224 blocks
    k_sa<<<g3, 256>>>(wsp);
    k_final<<<(B_ * C_ * QF8_) / 256, 256>>>(x, out);   // 3136 blocks
}

// round 15
// speedup vs baseline: 1.2394x; 1.2394x over previous
#include <cuda_runtime.h>
#include <math.h>

#define B_ 32
#define C_ 256
#define H_ 56
#define W_ 56
#define HW_ (H_*W_)          // 3136
#define R_ 16
#define HW4_ (HW_/4)         // 784
#define HW8_ (HW_/8)         // 392 float8 per plane
#define QF8_ 98              // f8 stride for 4-per-thread final (392/4)
#define CG_ 32               // channels per group
#define NCG_ 8               // channel groups
#define W8_ (W_/8)           // 7 f8 per row

// Scratch — 32B aligned
__device__ __align__(32) float g_avg[B_*C_];
__device__ __align__(32) float g_max[B_*C_];
__device__ __align__(32) float g_ca [B_*C_];
__device__ __align__(32) float g_ps [B_*NCG_*HW_];
__device__ __align__(32) float g_pm [B_*NCG_*HW_];
__device__ __align__(32) float g_pla[B_*HW_];   // merged channel-avg
__device__ __align__(32) float g_plm[B_*HW_];   // merged channel-max
__device__ __align__(32) float g_sa [B_*HW_];

// ---- 32-byte loads ----------------------------------------------------------
__device__ __forceinline__ void ldg8(const float* p, float4& lo, float4& hi) {
    unsigned long long r0, r1, r2, r3;
    asm volatile("ld.global.nc.v4.b64 {%0,%1,%2,%3}, [%4];"
                 : "=l"(r0), "=l"(r1), "=l"(r2), "=l"(r3) : "l"(p));
    lo.x = __uint_as_float((unsigned)r0); lo.y = __uint_as_float((unsigned)(r0 >> 32));
    lo.z = __uint_as_float((unsigned)r1); lo.w = __uint_as_float((unsigned)(r1 >> 32));
    hi.x = __uint_as_float((unsigned)r2); hi.y = __uint_as_float((unsigned)(r2 >> 32));
    hi.z = __uint_as_float((unsigned)r3); hi.w = __uint_as_float((unsigned)(r3 >> 32));
}
__device__ __forceinline__ void ldg_evl8(const float* p, float4& lo, float4& hi) {
    unsigned long long r0, r1, r2, r3;
    asm volatile("ld.global.nc.L2::evict_last.v4.b64 {%0,%1,%2,%3}, [%4];"
                 : "=l"(r0), "=l"(r1), "=l"(r2), "=l"(r3) : "l"(p));
    lo.x = __uint_as_float((unsigned)r0); lo.y = __uint_as_float((unsigned)(r0 >> 32));
    lo.z = __uint_as_float((unsigned)r1); lo.w = __uint_as_float((unsigned)(r1 >> 32));
    hi.x = __uint_as_float((unsigned)r2); hi.y = __uint_as_float((unsigned)(r2 >> 32));
    hi.z = __uint_as_float((unsigned)r3); hi.w = __uint_as_float((unsigned)(r3 >> 32));
}
__device__ __forceinline__ void ldg_evf8(const float* p, float4& lo, float4& hi) {
    unsigned long long r0, r1, r2, r3;
    asm volatile("ld.global.nc.L2::evict_first.v4.b64 {%0,%1,%2,%3}, [%4];"
                 : "=l"(r0), "=l"(r1), "=l"(r2), "=l"(r3) : "l"(p));
    lo.x = __uint_as_float((unsigned)r0); lo.y = __uint_as_float((unsigned)(r0 >> 32));
    lo.z = __uint_as_float((unsigned)r1); lo.w = __uint_as_float((unsigned)(r1 >> 32));
    hi.x = __uint_as_float((unsigned)r2); hi.y = __uint_as_float((unsigned)(r2 >> 32));
    hi.z = __uint_as_float((unsigned)r3); hi.w = __uint_as_float((unsigned)(r3 >> 32));
}

// ---------------------------------------------------------------------------
// Kernel 1: per-(b,c) spatial mean & max. One warp per plane, 32B loads.
// ---------------------------------------------------------------------------
__global__ __launch_bounds__(256) void k_spatial_pool(const float* __restrict__ x) {
    const int warp = threadIdx.x >> 5, lane = threadIdx.x & 31;
    const int bc = blockIdx.x * 8 + warp;
    const float* __restrict__ xp = x + (size_t)bc * HW_;
    float s = 0.f, m = -INFINITY;
    #pragma unroll
    for (int batch = 0; batch < 2; batch++) {
        float4 lo[6], hi[6];
        #pragma unroll
        for (int j = 0; j < 6; j++)
            ldg_evl8(xp + (size_t)(lane + 32 * (batch * 6 + j)) * 8, lo[j], hi[j]);
        #pragma unroll
        for (int j = 0; j < 6; j++) {
            s += ((lo[j].x + lo[j].y) + (lo[j].z + lo[j].w))
               + ((hi[j].x + hi[j].y) + (hi[j].z + hi[j].w));
            float m1 = fmaxf(fmaxf(lo[j].x, lo[j].y), fmaxf(lo[j].z, lo[j].w));
            float m2 = fmaxf(fmaxf(hi[j].x, hi[j].y), fmaxf(hi[j].z, hi[j].w));
            m = fmaxf(m, fmaxf(m1, m2));
        }
    }
    if (lane < 8) {
        float4 lo, hi;
        ldg_evl8(xp + (size_t)(384 + lane) * 8, lo, hi);
        s += ((lo.x + lo.y) + (lo.z + lo.w)) + ((hi.x + hi.y) + (hi.z + hi.w));
        float m1 = fmaxf(fmaxf(lo.x, lo.y), fmaxf(lo.z, lo.w));
        float m2 = fmaxf(fmaxf(hi.x, hi.y), fmaxf(hi.z, hi.w));
        m = fmaxf(m, fmaxf(m1, m2));
    }
    #pragma unroll
    for (int o = 16; o > 0; o >>= 1) {
        s += __shfl_xor_sync(0xffffffffu, s, o);
        m = fmaxf(m, __shfl_xor_sync(0xffffffffu, m, o));
    }
    if (lane == 0) {
        g_avg[bc] = s * (1.0f / HW_);
        g_max[bc] = m;
    }
}

// ---------------------------------------------------------------------------
// Kernel 1b: channel-attention MLP, one block per batch -> g_ca.
// ---------------------------------------------------------------------------
__global__ __launch_bounds__(256) void k_mlp(const float* __restrict__ w1,
                                             const float* __restrict__ w2) {
    const int b = blockIdx.x;
    const int t = threadIdx.x;
    __shared__ float sva[C_], svm[C_], hs[R_];
    sva[t] = g_avg[b * C_ + t];
    svm[t] = g_max[b * C_ + t];
    __syncthreads();
    {
        const int r = t >> 4, j = t & 15;
        const float* __restrict__ wr = w1 + r * C_ + j * 16;
        const float* __restrict__ va = sva + j * 16;
        const float* __restrict__ vm = svm + j * 16;
        float pa = 0.f, pmx = 0.f;
        #pragma unroll
        for (int i = 0; i < 16; i++) {
            pa  = fmaf(wr[i], va[i], pa);
            pmx = fmaf(wr[i], vm[i], pmx);
        }
        #pragma unroll
        for (int o = 8; o > 0; o >>= 1) {
            pa  += __shfl_down_sync(0xffffffffu, pa,  o, 16);
            pmx += __shfl_down_sync(0xffffffffu, pmx, o, 16);
        }
        if (j == 0) hs[r] = fmaxf(pa, 0.f) + fmaxf(pmx, 0.f);
    }
    __syncthreads();
    float o = 0.f;
    const float* __restrict__ w2r = w2 + t * R_;
    #pragma unroll
    for (int r = 0; r < R_; r++) o = fmaf(w2r[r], hs[r], o);
    g_ca[b * C_ + t] = 1.0f / (1.0f + __expf(-o));
}

// ---------------------------------------------------------------------------
// Kernel 2: partial channel mean/max of x*ca. grid (2, 8, 32) = 512 blocks.
// (exact R13 code — proven)
// ---------------------------------------------------------------------------
__global__ __launch_bounds__(256, 2) void k_chan_pool(const float* __restrict__ x) {
    const int chunk = blockIdx.x, cg = blockIdx.y, b = blockIdx.z;
    const int t = threadIdx.x;
    __shared__ float sca[C_];
    sca[t] = g_ca[b * C_ + t];
    __syncthreads();

    const int f8 = chunk * 256 + t;
    if (f8 >= HW8_) return;
    const float* __restrict__ xb =
        x + (size_t)b * C_ * HW_ + (size_t)cg * CG_ * HW_ + (size_t)f8 * 8;
    const float* __restrict__ scg = sca + cg * CG_;
    float4 slo = make_float4(0.f, 0.f, 0.f, 0.f), shi = slo;
    float4 mlo = make_float4(-INFINITY, -INFINITY, -INFINITY, -INFINITY), mhi = mlo;
    #pragma unroll
    for (int batch = 0; batch < 4; batch++) {
        float4 lo[8], hi[8];
        #pragma unroll
        for (int j = 0; j < 8; j++)
            ldg_evl8(xb + (size_t)(batch * 8 + j) * HW_, lo[j], hi[j]);
        #pragma unroll
        for (int j = 0; j < 8; j++) {
            const float a = scg[batch * 8 + j];
            float v0 = lo[j].x * a, v1 = lo[j].y * a, v2 = lo[j].z * a, v3 = lo[j].w * a;
            float v4 = hi[j].x * a, v5 = hi[j].y * a, v6 = hi[j].z * a, v7 = hi[j].w * a;
            slo.x += v0; slo.y += v1; slo.z += v2; slo.w += v3;
            shi.x += v4; shi.y += v5; shi.z += v6; shi.w += v7;
            mlo.x = fmaxf(mlo.x, v0); mlo.y = fmaxf(mlo.y, v1);
            mlo.z = fmaxf(mlo.z, v2); mlo.w = fmaxf(mlo.w, v3);
            mhi.x = fmaxf(mhi.x, v4); mhi.y = fmaxf(mhi.y, v5);
            mhi.z = fmaxf(mhi.z, v6); mhi.w = fmaxf(mhi.w, v7);
        }
    }
    const size_t base = ((size_t)b * NCG_ + cg) * HW_;
    float4* __restrict__ pav = (float4*)(g_ps + base);
    float4* __restrict__ pmx = (float4*)(g_pm + base);
    pav[f8 * 2]     = slo;
    pav[f8 * 2 + 1] = shi;
    pmx[f8 * 2]     = mlo;
    pmx[f8 * 2 + 1] = mhi;
}

// ---------------------------------------------------------------------------
// Kernel 2b: merge partials ONCE per position (no halo redundancy).
// One thread per (b, f4): 25088 threads = 98 blocks. All loads/stores coalesced.
// ---------------------------------------------------------------------------
__global__ __launch_bounds__(256) void k_merge() {
    const int id = blockIdx.x * 256 + threadIdx.x;    // 0..25087
    const int b  = id / HW4_;
    const int p4 = id - b * HW4_;
    const float4* __restrict__ ps = (const float4*)(g_ps + (size_t)b * NCG_ * HW_) + p4;
    const float4* __restrict__ pm = (const float4*)(g_pm + (size_t)b * NCG_ * HW_) + p4;
    float4 vs[NCG_], vm[NCG_];
    #pragma unroll
    for (int g = 0; g < NCG_; g++) vs[g] = __ldg(ps + g * HW4_);
    #pragma unroll
    for (int g = 0; g < NCG_; g++) vm[g] = __ldg(pm + g * HW4_);
    float4 s = vs[0], m = vm[0];
    #pragma unroll
    for (int g = 1; g < NCG_; g++) {
        s.x += vs[g].x; s.y += vs[g].y; s.z += vs[g].z; s.w += vs[g].w;
        m.x = fmaxf(m.x, vm[g].x); m.y = fmaxf(m.y, vm[g].y);
        m.z = fmaxf(m.z, vm[g].z); m.w = fmaxf(m.w, vm[g].w);
    }
    const float inv = 1.0f / C_;
    s.x *= inv; s.y *= inv; s.z *= inv; s.w *= inv;
    ((float4*)(g_pla + (size_t)b * HW_))[p4] = s;
    ((float4*)(g_plm + (size_t)b * HW_))[p4] = m;
}

// ---------------------------------------------------------------------------
// Kernel 3: 7x7 conv + sigmoid on merged pooled -> g_sa.
// TR=8: grid (7, 32) = 224 blocks x 256 threads. Halo load is trivial now.
// ---------------------------------------------------------------------------
#define TR 8
#define HR (TR + 6)                // 14 halo rows
#define HF8 (HR * W_ / 8)          // 98 float8 in halo tile

__global__ __launch_bounds__(256) void k_sa(const float* __restrict__ wsp) {
    const int b  = blockIdx.y;
    const int h0 = blockIdx.x * TR;
    const int t  = threadIdx.x;

    __shared__ float sw[98];
    __shared__ __align__(32) float spa[HR * W_];
    __shared__ __align__(32) float spm[HR * W_];

    if (t < 98) sw[t] = wsp[t];

    // halo load: threads 0..97 load spa (avg), threads 128..225 load spm (max)
    const int half = t >> 7;
    const int idx  = t & 127;
    if (idx < HF8) {
        const int r  = idx / W8_;
        const int c8 = idx - r * W8_;
        const int hh = h0 - 3 + r;
        float4 lo = make_float4(0.f, 0.f, 0.f, 0.f), hi = lo;
        if (hh >= 0 && hh < H_) {
            const float* __restrict__ src = (half ? g_plm : g_pla)
                                          + (size_t)b * HW_ + (size_t)(hh * W8_ + c8) * 8;
            ldg8(src, lo, hi);
        }
        float* dst = half ? spm : spa;
        ((float4*)dst)[idx * 2]     = lo;
        ((float4*)dst)[idx * 2 + 1] = hi;
    }
    __syncthreads();

    for (int p = t; p < TR * W_; p += 256) {
        const int hr = p / W_;
        const int wd = p - hr * W_;
        const int h  = h0 + hr;
        float acc = 0.f;
        #pragma unroll
        for (int kh = 0; kh < 7; kh++) {
            const int hh = h + kh - 3;
            if (hh < 0 || hh >= H_) continue;
            const int sr = hh - (h0 - 3);   // 0..13
            #pragma unroll
            for (int kw = 0; kw < 7; kw++) {
                const int ww = wd + kw - 3;
                if (ww < 0 || ww >= W_) continue;
                acc = fmaf(sw[kh * 7 + kw],      spa[sr * W_ + ww], acc);
                acc = fmaf(sw[49 + kh * 7 + kw], spm[sr * W_ + ww], acc);
            }
        }
        g_sa[b * HW_ + h * W_ + wd] = 1.0f / (1.0f + __expf(-acc));
    }
}

// ---------------------------------------------------------------------------
// Kernel 4: out = x * (1 + ca*sa). 4 f8 per thread (stride 98 f8 in-plane).
// ---------------------------------------------------------------------------
__global__ __launch_bounds__(256) void k_final(const float* __restrict__ x,
                                               float* __restrict__ out) {
    const int g = blockIdx.x * 256 + threadIdx.x;
    const int plane = g / QF8_;
    const int r = g - plane * QF8_;
    const int b = plane >> 8;
    const float ca = __ldg(&g_ca[plane]);
    const float*  __restrict__ xs = x + (size_t)plane * HW_ + (size_t)r * 8;
    const float4* __restrict__ ss = (const float4*)(g_sa + (size_t)b * HW_) + r * 2;
    float4*       __restrict__ os = (float4*)(out + (size_t)plane * HW_) + r * 2;

    float4 vlo[4], vhi[4], slo[4], shi[4];
    #pragma unroll
    for (int j = 0; j < 4; j++)
        ldg_evf8(xs + (size_t)j * QF8_ * 8, vlo[j], vhi[j]);
    #pragma unroll
    for (int j = 0; j < 4; j++) {
        slo[j] = __ldg(ss + j * QF8_ * 2);
        shi[j] = __ldg(ss + j * QF8_ * 2 + 1);
    }
    #pragma unroll
    for (int j = 0; j < 4; j++) {
        float4 o1, o2;
        o1.x = vlo[j].x * fmaf(ca, slo[j].x, 1.0f);
        o1.y = vlo[j].y * fmaf(ca, slo[j].y, 1.0f);
        o1.z = vlo[j].z * fmaf(ca, slo[j].z, 1.0f);
        o1.w = vlo[j].w * fmaf(ca, slo[j].w, 1.0f);
        o2.x = vhi[j].x * fmaf(ca, shi[j].x, 1.0f);
        o2.y = vhi[j].y * fmaf(ca, shi[j].y, 1.0f);
        o2.z = vhi[j].z * fmaf(ca, shi[j].z, 1.0f);
        o2.w = vhi[j].w * fmaf(ca, shi[j].w, 1.0f);
        os[j * QF8_ * 2]     = o1;
        os[j * QF8_ * 2 + 1] = o2;
    }
}

// ---------------------------------------------------------------------------
extern "C" void kernel_launch(void* const* d_in, const int* in_sizes, int n_in,
                              void* d_out, int out_size) {
    const float* x   = (const float*)d_in[0];
    const float* w1  = (const float*)d_in[1];
    const float* w2  = (const float*)d_in[2];
    const float* wsp = (const float*)d_in[3];
    float* out = (float*)d_out;

    k_spatial_pool<<<1024, 256>>>(x);
    k_mlp<<<B_, 256>>>(w1, w2);
    dim3 g2((HW8_ + 255) / 256, NCG_, B_);       // (2, 8, 32) = 512 blocks
    k_chan_pool<<<g2, 256>>>(x);
    k_merge<<<(B_ * HW4_) / 256, 256>>>();       // 98 blocks
    dim3 g3(H_ / TR, B_);                        // (7, 32) = 224 blocks
    k_sa<<<g3, 256>>>(wsp);
    k_final<<<(B_ * C_ * QF8_) / 256, 256>>>(x, out);   // 3136 blocks
}

// round 16
// speedup vs baseline: 1.2696x; 1.0244x over previous
#include <cuda_runtime.h>
#include <math.h>

#define B_ 32
#define C_ 256
#define H_ 56
#define W_ 56
#define HW_ (H_*W_)          // 3136
#define R_ 16
#define HW4_ (HW_/4)         // 784
#define HW8_ (HW_/8)         // 392 float8 per plane
#define QF8_ 98              // f8 stride for 4-per-thread final (392/4)
#define CG_ 32               // channels per group
#define NCG_ 8               // channel groups
#define W8_ (W_/8)           // 7 f8 per row

// Scratch — 32B aligned
__device__ __align__(32) float g_avg[B_*C_];
__device__ __align__(32) float g_max[B_*C_];
__device__ __align__(32) float g_ca [B_*C_];
__device__ __align__(32) float g_ps [B_*NCG_*HW_];
__device__ __align__(32) float g_pm [B_*NCG_*HW_];
__device__ __align__(32) float g_sa [B_*HW_];

// ---- 32-byte memory ops ------------------------------------------------------
__device__ __forceinline__ void ldg8(const float* p, float4& lo, float4& hi) {
    unsigned long long r0, r1, r2, r3;
    asm volatile("ld.global.nc.v4.b64 {%0,%1,%2,%3}, [%4];"
                 : "=l"(r0), "=l"(r1), "=l"(r2), "=l"(r3) : "l"(p));
    lo.x = __uint_as_float((unsigned)r0); lo.y = __uint_as_float((unsigned)(r0 >> 32));
    lo.z = __uint_as_float((unsigned)r1); lo.w = __uint_as_float((unsigned)(r1 >> 32));
    hi.x = __uint_as_float((unsigned)r2); hi.y = __uint_as_float((unsigned)(r2 >> 32));
    hi.z = __uint_as_float((unsigned)r3); hi.w = __uint_as_float((unsigned)(r3 >> 32));
}
__device__ __forceinline__ void ldg_evl8(const float* p, float4& lo, float4& hi) {
    unsigned long long r0, r1, r2, r3;
    asm volatile("ld.global.nc.L2::evict_last.v4.b64 {%0,%1,%2,%3}, [%4];"
                 : "=l"(r0), "=l"(r1), "=l"(r2), "=l"(r3) : "l"(p));
    lo.x = __uint_as_float((unsigned)r0); lo.y = __uint_as_float((unsigned)(r0 >> 32));
    lo.z = __uint_as_float((unsigned)r1); lo.w = __uint_as_float((unsigned)(r1 >> 32));
    hi.x = __uint_as_float((unsigned)r2); hi.y = __uint_as_float((unsigned)(r2 >> 32));
    hi.z = __uint_as_float((unsigned)r3); hi.w = __uint_as_float((unsigned)(r3 >> 32));
}
__device__ __forceinline__ void ldg_evf8(const float* p, float4& lo, float4& hi) {
    unsigned long long r0, r1, r2, r3;
    asm volatile("ld.global.nc.L2::evict_first.v4.b64 {%0,%1,%2,%3}, [%4];"
                 : "=l"(r0), "=l"(r1), "=l"(r2), "=l"(r3) : "l"(p));
    lo.x = __uint_as_float((unsigned)r0); lo.y = __uint_as_float((unsigned)(r0 >> 32));
    lo.z = __uint_as_float((unsigned)r1); lo.w = __uint_as_float((unsigned)(r1 >> 32));
    hi.x = __uint_as_float((unsigned)r2); hi.y = __uint_as_float((unsigned)(r2 >> 32));
    hi.z = __uint_as_float((unsigned)r3); hi.w = __uint_as_float((unsigned)(r3 >> 32));
}
// store with evict_last — keep the partials resident in L2 for k_sa
__device__ __forceinline__ void stg_evl8(float* p, float4 lo, float4 hi) {
    unsigned long long r0 = ((unsigned long long)__float_as_uint(lo.y) << 32) | __float_as_uint(lo.x);
    unsigned long long r1 = ((unsigned long long)__float_as_uint(lo.w) << 32) | __float_as_uint(lo.z);
    unsigned long long r2 = ((unsigned long long)__float_as_uint(hi.y) << 32) | __float_as_uint(hi.x);
    unsigned long long r3 = ((unsigned long long)__float_as_uint(hi.w) << 32) | __float_as_uint(hi.z);
    asm volatile("st.global.L2::evict_last.v4.b64 [%0], {%1,%2,%3,%4};"
                 :: "l"(p), "l"(r0), "l"(r1), "l"(r2), "l"(r3) : "memory");
}

// ---------------------------------------------------------------------------
// Kernel 1: per-(b,c) spatial mean & max. One warp per plane, 32B loads.
// ---------------------------------------------------------------------------
__global__ __launch_bounds__(256) void k_spatial_pool(const float* __restrict__ x) {
    const int warp = threadIdx.x >> 5, lane = threadIdx.x & 31;
    const int bc = blockIdx.x * 8 + warp;
    const float* __restrict__ xp = x + (size_t)bc * HW_;
    float s = 0.f, m = -INFINITY;
    #pragma unroll
    for (int batch = 0; batch < 2; batch++) {
        float4 lo[6], hi[6];
        #pragma unroll
        for (int j = 0; j < 6; j++)
            ldg_evl8(xp + (size_t)(lane + 32 * (batch * 6 + j)) * 8, lo[j], hi[j]);
        #pragma unroll
        for (int j = 0; j < 6; j++) {
            s += ((lo[j].x + lo[j].y) + (lo[j].z + lo[j].w))
               + ((hi[j].x + hi[j].y) + (hi[j].z + hi[j].w));
            float m1 = fmaxf(fmaxf(lo[j].x, lo[j].y), fmaxf(lo[j].z, lo[j].w));
            float m2 = fmaxf(fmaxf(hi[j].x, hi[j].y), fmaxf(hi[j].z, hi[j].w));
            m = fmaxf(m, fmaxf(m1, m2));
        }
    }
    if (lane < 8) {
        float4 lo, hi;
        ldg_evl8(xp + (size_t)(384 + lane) * 8, lo, hi);
        s += ((lo.x + lo.y) + (lo.z + lo.w)) + ((hi.x + hi.y) + (hi.z + hi.w));
        float m1 = fmaxf(fmaxf(lo.x, lo.y), fmaxf(lo.z, lo.w));
        float m2 = fmaxf(fmaxf(hi.x, hi.y), fmaxf(hi.z, hi.w));
        m = fmaxf(m, fmaxf(m1, m2));
    }
    #pragma unroll
    for (int o = 16; o > 0; o >>= 1) {
        s += __shfl_xor_sync(0xffffffffu, s, o);
        m = fmaxf(m, __shfl_xor_sync(0xffffffffu, m, o));
    }
    if (lane == 0) {
        g_avg[bc] = s * (1.0f / HW_);
        g_max[bc] = m;
    }
}

// ---------------------------------------------------------------------------
// Kernel 1b: channel-attention MLP, one block per batch -> g_ca.
// ---------------------------------------------------------------------------
__global__ __launch_bounds__(256) void k_mlp(const float* __restrict__ w1,
                                             const float* __restrict__ w2) {
    const int b = blockIdx.x;
    const int t = threadIdx.x;
    __shared__ float sva[C_], svm[C_], hs[R_];
    sva[t] = g_avg[b * C_ + t];
    svm[t] = g_max[b * C_ + t];
    __syncthreads();
    {
        const int r = t >> 4, j = t & 15;
        const float* __restrict__ wr = w1 + r * C_ + j * 16;
        const float* __restrict__ va = sva + j * 16;
        const float* __restrict__ vm = svm + j * 16;
        float pa = 0.f, pmx = 0.f;
        #pragma unroll
        for (int i = 0; i < 16; i++) {
            pa  = fmaf(wr[i], va[i], pa);
            pmx = fmaf(wr[i], vm[i], pmx);
        }
        #pragma unroll
        for (int o = 8; o > 0; o >>= 1) {
            pa  += __shfl_down_sync(0xffffffffu, pa,  o, 16);
            pmx += __shfl_down_sync(0xffffffffu, pmx, o, 16);
        }
        if (j == 0) hs[r] = fmaxf(pa, 0.f) + fmaxf(pmx, 0.f);
    }
    __syncthreads();
    float o = 0.f;
    const float* __restrict__ w2r = w2 + t * R_;
    #pragma unroll
    for (int r = 0; r < R_; r++) o = fmaf(w2r[r], hs[r], o);
    g_ca[b * C_ + t] = 1.0f / (1.0f + __expf(-o));
}

// ---------------------------------------------------------------------------
// Kernel 2: partial channel mean/max of x*ca. grid (2, 8, 32) = 512 blocks.
// Partials stored with evict_last so they survive in L2 until k_sa.
// ---------------------------------------------------------------------------
__global__ __launch_bounds__(256, 2) void k_chan_pool(const float* __restrict__ x) {
    const int chunk = blockIdx.x, cg = blockIdx.y, b = blockIdx.z;
    const int t = threadIdx.x;
    __shared__ float sca[C_];
    sca[t] = g_ca[b * C_ + t];
    __syncthreads();

    const int f8 = chunk * 256 + t;
    if (f8 >= HW8_) return;
    const float* __restrict__ xb =
        x + (size_t)b * C_ * HW_ + (size_t)cg * CG_ * HW_ + (size_t)f8 * 8;
    const float* __restrict__ scg = sca + cg * CG_;
    float4 slo = make_float4(0.f, 0.f, 0.f, 0.f), shi = slo;
    float4 mlo = make_float4(-INFINITY, -INFINITY, -INFINITY, -INFINITY), mhi = mlo;
    #pragma unroll
    for (int batch = 0; batch < 4; batch++) {
        float4 lo[8], hi[8];
        #pragma unroll
        for (int j = 0; j < 8; j++)
            ldg_evl8(xb + (size_t)(batch * 8 + j) * HW_, lo[j], hi[j]);
        #pragma unroll
        for (int j = 0; j < 8; j++) {
            const float a = scg[batch * 8 + j];
            float v0 = lo[j].x * a, v1 = lo[j].y * a, v2 = lo[j].z * a, v3 = lo[j].w * a;
            float v4 = hi[j].x * a, v5 = hi[j].y * a, v6 = hi[j].z * a, v7 = hi[j].w * a;
            slo.x += v0; slo.y += v1; slo.z += v2; slo.w += v3;
            shi.x += v4; shi.y += v5; shi.z += v6; shi.w += v7;
            mlo.x = fmaxf(mlo.x, v0); mlo.y = fmaxf(mlo.y, v1);
            mlo.z = fmaxf(mlo.z, v2); mlo.w = fmaxf(mlo.w, v3);
            mhi.x = fmaxf(mhi.x, v4); mhi.y = fmaxf(mhi.y, v5);
            mhi.z = fmaxf(mhi.z, v6); mhi.w = fmaxf(mhi.w, v7);
        }
    }
    const size_t base = ((size_t)b * NCG_ + cg) * HW_;
    stg_evl8(g_ps + base + (size_t)f8 * 8, slo, shi);
    stg_evl8(g_pm + base + (size_t)f8 * 8, mlo, mhi);
}

// ---------------------------------------------------------------------------
// Kernel 3: merge partials + 7x7 conv + sigmoid -> g_sa.
// TR=8: grid (7, 32) = 224 blocks x 256 threads. (R13 structure)
// ---------------------------------------------------------------------------
#define TR 8
#define HR (TR + 6)                // 14 halo rows
#define HF8 (HR * W_ / 8)          // 98 float8 in halo tile

__global__ __launch_bounds__(256) void k_sa(const float* __restrict__ wsp) {
    const int b  = blockIdx.y;
    const int h0 = blockIdx.x * TR;
    const int t  = threadIdx.x;

    __shared__ float sw[98];
    __shared__ __align__(32) float spa[HR * W_];
    __shared__ __align__(32) float spm[HR * W_];

    if (t >= 128 && t < 226) sw[t - 128] = wsp[t - 128];

    if (t < HF8) {
        const int r  = t / W8_;            // halo row 0..13
        const int c8 = t - r * W8_;        // f8 column 0..6
        const int hh = h0 - 3 + r;
        float4 slo = make_float4(0.f, 0.f, 0.f, 0.f), shi = slo;
        float4 mlo = slo, mhi = slo;
        if (hh >= 0 && hh < H_) {
            const size_t p = (size_t)(hh * W8_ + c8) * 8;
            const float* __restrict__ ps = g_ps + (size_t)b * NCG_ * HW_ + p;
            const float* __restrict__ pm = g_pm + (size_t)b * NCG_ * HW_ + p;
            {
                float4 lo[NCG_], hi[NCG_];
                #pragma unroll
                for (int g = 0; g < NCG_; g++) ldg8(ps + (size_t)g * HW_, lo[g], hi[g]);
                slo = lo[0]; shi = hi[0];
                #pragma unroll
                for (int g = 1; g < NCG_; g++) {
                    slo.x += lo[g].x; slo.y += lo[g].y; slo.z += lo[g].z; slo.w += lo[g].w;
                    shi.x += hi[g].x; shi.y += hi[g].y; shi.z += hi[g].z; shi.w += hi[g].w;
                }
                const float inv = 1.0f / C_;
                slo.x *= inv; slo.y *= inv; slo.z *= inv; slo.w *= inv;
                shi.x *= inv; shi.y *= inv; shi.z *= inv; shi.w *= inv;
            }
            {
                float4 lo[NCG_], hi[NCG_];
                #pragma unroll
                for (int g = 0; g < NCG_; g++) ldg8(pm + (size_t)g * HW_, lo[g], hi[g]);
                mlo = lo[0]; mhi = hi[0];
                #pragma unroll
                for (int g = 1; g < NCG_; g++) {
                    mlo.x = fmaxf(mlo.x, lo[g].x); mlo.y = fmaxf(mlo.y, lo[g].y);
                    mlo.z = fmaxf(mlo.z, lo[g].z); mlo.w = fmaxf(mlo.w, lo[g].w);
                    mhi.x = fmaxf(mhi.x, hi[g].x); mhi.y = fmaxf(mhi.y, hi[g].y);
                    mhi.z = fmaxf(mhi.z, hi[g].z); mhi.w = fmaxf(mhi.w, hi[g].w);
                }
            }
        }
        ((float4*)spa)[t * 2]     = slo;
        ((float4*)spa)[t * 2 + 1] = shi;
        ((float4*)spm)[t * 2]     = mlo;
        ((float4*)spm)[t * 2 + 1] = mhi;
    }
    __syncthreads();

    for (int p = t; p < TR * W_; p += 256) {
        const int hr = p / W_;
        const int wd = p - hr * W_;
        const int h  = h0 + hr;
        float acc = 0.f;
        #pragma unroll
        for (int kh = 0; kh < 7; kh++) {
            const int hh = h + kh - 3;
            if (hh < 0 || hh >= H_) continue;
            const int sr = hh - (h0 - 3);   // 0..13
            #pragma unroll
            for (int kw = 0; kw < 7; kw++) {
                const int ww = wd + kw - 3;
                if (ww < 0 || ww >= W_) continue;
                acc = fmaf(sw[kh * 7 + kw],      spa[sr * W_ + ww], acc);
                acc = fmaf(sw[49 + kh * 7 + kw], spm[sr * W_ + ww], acc);
            }
        }
        g_sa[b * HW_ + h * W_ + wd] = 1.0f / (1.0f + __expf(-acc));
    }
}

// ---------------------------------------------------------------------------
// Kernel 4: out = x * (1 + ca*sa). 4 f8 per thread (stride 98 f8 in-plane).
// ---------------------------------------------------------------------------
__global__ __launch_bounds__(256) void k_final(const float* __restrict__ x,
                                               float* __restrict__ out) {
    const int g = blockIdx.x * 256 + threadIdx.x;
    const int plane = g / QF8_;
    const int r = g - plane * QF8_;
    const int b = plane >> 8;
    const float ca = __ldg(&g_ca[plane]);
    const float*  __restrict__ xs = x + (size_t)plane * HW_ + (size_t)r * 8;
    const float4* __restrict__ ss = (const float4*)(g_sa + (size_t)b * HW_) + r * 2;
    float4*       __restrict__ os = (float4*)(out + (size_t)plane * HW_) + r * 2;

    float4 vlo[4], vhi[4], slo[4], shi[4];
    #pragma unroll
    for (int j = 0; j < 4; j++)
        ldg_evf8(xs + (size_t)j * QF8_ * 8, vlo[j], vhi[j]);
    #pragma unroll
    for (int j = 0; j < 4; j++) {
        slo[j] = __ldg(ss + j * QF8_ * 2);
        shi[j] = __ldg(ss + j * QF8_ * 2 + 1);
    }
    #pragma unroll
    for (int j = 0; j < 4; j++) {
        float4 o1, o2;
        o1.x = vlo[j].x * fmaf(ca, slo[j].x, 1.0f);
        o1.y = vlo[j].y * fmaf(ca, slo[j].y, 1.0f);
        o1.z = vlo[j].z * fmaf(ca, slo[j].z, 1.0f);
        o1.w = vlo[j].w * fmaf(ca, slo[j].w, 1.0f);
        o2.x = vhi[j].x * fmaf(ca, shi[j].x, 1.0f);
        o2.y = vhi[j].y * fmaf(ca, shi[j].y, 1.0f);
        o2.z = vhi[j].z * fmaf(ca, shi[j].z, 1.0f);
        o2.w = vhi[j].w * fmaf(ca, shi[j].w, 1.0f);
        os[j * QF8_ * 2]     = o1;
        os[j * QF8_ * 2 + 1] = o2;
    }
}

// ---------------------------------------------------------------------------
extern "C" void kernel_launch(void* const* d_in, const int* in_sizes, int n_in,
                              void* d_out, int out_size) {
    const float* x   = (const float*)d_in[0];
    const float* w1  = (const float*)d_in[1];
    const float* w2  = (const float*)d_in[2];
    const float* wsp = (const float*)d_in[3];
    float* out = (float*)d_out;

    k_spatial_pool<<<1024, 256>>>(x);
    k_mlp<<<B_, 256>>>(w1, w2);
    dim3 g2((HW8_ + 255) / 256, NCG_, B_);       // (2, 8, 32) = 512 blocks
    k_chan_pool<<<g2, 256>>>(x);
    dim3 g3(H_ / TR, B_);                        // (7, 32) = 224 blocks
    k_sa<<<g3, 256>>>(wsp);
    k_final<<<(B_ * C_ * QF8_) / 256, 256>>>(x, out);   // 3136 blocks
}

// round 17
// speedup vs baseline: 1.2701x; 1.0004x over previous
#include <cuda_runtime.h>
#include <math.h>

#define B_ 32
#define C_ 256
#define H_ 56
#define W_ 56
#define HW_ (H_*W_)          // 3136
#define R_ 16
#define HW4_ (HW_/4)         // 784
#define HW8_ (HW_/8)         // 392 float8 per plane
#define QF8_ 98              // f8 stride for 4-per-thread final (392/4)
#define CG_ 32               // channels per group
#define NCG_ 8               // channel groups
#define W8_ (W_/8)           // 7 f8 per row

// Scratch — 32B aligned
__device__ __align__(32) float g_avg[B_*C_];
__device__ __align__(32) float g_max[B_*C_];
__device__ __align__(32) float g_ca [B_*C_];
__device__ __align__(32) float g_ps [B_*NCG_*HW_];
__device__ __align__(32) float g_pm [B_*NCG_*HW_];
__device__ __align__(32) float g_sa [B_*HW_];

// ---- 32-byte memory ops ------------------------------------------------------
__device__ __forceinline__ void ldg8(const float* p, float4& lo, float4& hi) {
    unsigned long long r0, r1, r2, r3;
    asm volatile("ld.global.nc.v4.b64 {%0,%1,%2,%3}, [%4];"
                 : "=l"(r0), "=l"(r1), "=l"(r2), "=l"(r3) : "l"(p));
    lo.x = __uint_as_float((unsigned)r0); lo.y = __uint_as_float((unsigned)(r0 >> 32));
    lo.z = __uint_as_float((unsigned)r1); lo.w = __uint_as_float((unsigned)(r1 >> 32));
    hi.x = __uint_as_float((unsigned)r2); hi.y = __uint_as_float((unsigned)(r2 >> 32));
    hi.z = __uint_as_float((unsigned)r3); hi.w = __uint_as_float((unsigned)(r3 >> 32));
}
__device__ __forceinline__ void ldg_evl8(const float* p, float4& lo, float4& hi) {
    unsigned long long r0, r1, r2, r3;
    asm volatile("ld.global.nc.L2::evict_last.v4.b64 {%0,%1,%2,%3}, [%4];"
                 : "=l"(r0), "=l"(r1), "=l"(r2), "=l"(r3) : "l"(p));
    lo.x = __uint_as_float((unsigned)r0); lo.y = __uint_as_float((unsigned)(r0 >> 32));
    lo.z = __uint_as_float((unsigned)r1); lo.w = __uint_as_float((unsigned)(r1 >> 32));
    hi.x = __uint_as_float((unsigned)r2); hi.y = __uint_as_float((unsigned)(r2 >> 32));
    hi.z = __uint_as_float((unsigned)r3); hi.w = __uint_as_float((unsigned)(r3 >> 32));
}
__device__ __forceinline__ void ldg_evf8(const float* p, float4& lo, float4& hi) {
    unsigned long long r0, r1, r2, r3;
    asm volatile("ld.global.nc.L2::evict_first.v4.b64 {%0,%1,%2,%3}, [%4];"
                 : "=l"(r0), "=l"(r1), "=l"(r2), "=l"(r3) : "l"(p));
    lo.x = __uint_as_float((unsigned)r0); lo.y = __uint_as_float((unsigned)(r0 >> 32));
    lo.z = __uint_as_float((unsigned)r1); lo.w = __uint_as_float((unsigned)(r1 >> 32));
    hi.x = __uint_as_float((unsigned)r2); hi.y = __uint_as_float((unsigned)(r2 >> 32));
    hi.z = __uint_as_float((unsigned)r3); hi.w = __uint_as_float((unsigned)(r3 >> 32));
}
__device__ __forceinline__ void stg_evl8(float* p, float4 lo, float4 hi) {
    unsigned long long r0 = ((unsigned long long)__float_as_uint(lo.y) << 32) | __float_as_uint(lo.x);
    unsigned long long r1 = ((unsigned long long)__float_as_uint(lo.w) << 32) | __float_as_uint(lo.z);
    unsigned long long r2 = ((unsigned long long)__float_as_uint(hi.y) << 32) | __float_as_uint(hi.x);
    unsigned long long r3 = ((unsigned long long)__float_as_uint(hi.w) << 32) | __float_as_uint(hi.z);
    asm volatile("st.global.L2::evict_last.v4.b64 [%0], {%1,%2,%3,%4};"
                 :: "l"(p), "l"(r0), "l"(r1), "l"(r2), "l"(r3) : "memory");
}

// ---------------------------------------------------------------------------
// Kernel 1: per-(b,c) spatial mean & max. One warp per plane, 32B loads.
// ---------------------------------------------------------------------------
__global__ __launch_bounds__(256) void k_spatial_pool(const float* __restrict__ x) {
    const int warp = threadIdx.x >> 5, lane = threadIdx.x & 31;
    const int bc = blockIdx.x * 8 + warp;
    const float* __restrict__ xp = x + (size_t)bc * HW_;
    float s = 0.f, m = -INFINITY;
    #pragma unroll
    for (int batch = 0; batch < 2; batch++) {
        float4 lo[6], hi[6];
        #pragma unroll
        for (int j = 0; j < 6; j++)
            ldg_evl8(xp + (size_t)(lane + 32 * (batch * 6 + j)) * 8, lo[j], hi[j]);
        #pragma unroll
        for (int j = 0; j < 6; j++) {
            s += ((lo[j].x + lo[j].y) + (lo[j].z + lo[j].w))
               + ((hi[j].x + hi[j].y) + (hi[j].z + hi[j].w));
            float m1 = fmaxf(fmaxf(lo[j].x, lo[j].y), fmaxf(lo[j].z, lo[j].w));
            float m2 = fmaxf(fmaxf(hi[j].x, hi[j].y), fmaxf(hi[j].z, hi[j].w));
            m = fmaxf(m, fmaxf(m1, m2));
        }
    }
    if (lane < 8) {
        float4 lo, hi;
        ldg_evl8(xp + (size_t)(384 + lane) * 8, lo, hi);
        s += ((lo.x + lo.y) + (lo.z + lo.w)) + ((hi.x + hi.y) + (hi.z + hi.w));
        float m1 = fmaxf(fmaxf(lo.x, lo.y), fmaxf(lo.z, lo.w));
        float m2 = fmaxf(fmaxf(hi.x, hi.y), fmaxf(hi.z, hi.w));
        m = fmaxf(m, fmaxf(m1, m2));
    }
    #pragma unroll
    for (int o = 16; o > 0; o >>= 1) {
        s += __shfl_xor_sync(0xffffffffu, s, o);
        m = fmaxf(m, __shfl_xor_sync(0xffffffffu, m, o));
    }
    if (lane == 0) {
        g_avg[bc] = s * (1.0f / HW_);
        g_max[bc] = m;
    }
}

// ---------------------------------------------------------------------------
// Kernel 1b: channel-attention MLP, one block per batch -> g_ca.
// ---------------------------------------------------------------------------
__global__ __launch_bounds__(256) void k_mlp(const float* __restrict__ w1,
                                             const float* __restrict__ w2) {
    const int b = blockIdx.x;
    const int t = threadIdx.x;
    __shared__ float sva[C_], svm[C_], hs[R_];
    sva[t] = g_avg[b * C_ + t];
    svm[t] = g_max[b * C_ + t];
    __syncthreads();
    {
        const int r = t >> 4, j = t & 15;
        const float* __restrict__ wr = w1 + r * C_ + j * 16;
        const float* __restrict__ va = sva + j * 16;
        const float* __restrict__ vm = svm + j * 16;
        float pa = 0.f, pmx = 0.f;
        #pragma unroll
        for (int i = 0; i < 16; i++) {
            pa  = fmaf(wr[i], va[i], pa);
            pmx = fmaf(wr[i], vm[i], pmx);
        }
        #pragma unroll
        for (int o = 8; o > 0; o >>= 1) {
            pa  += __shfl_down_sync(0xffffffffu, pa,  o, 16);
            pmx += __shfl_down_sync(0xffffffffu, pmx, o, 16);
        }
        if (j == 0) hs[r] = fmaxf(pa, 0.f) + fmaxf(pmx, 0.f);
    }
    __syncthreads();
    float o = 0.f;
    const float* __restrict__ w2r = w2 + t * R_;
    #pragma unroll
    for (int r = 0; r < R_; r++) o = fmaf(w2r[r], hs[r], o);
    g_ca[b * C_ + t] = 1.0f / (1.0f + __expf(-o));
}

// ---------------------------------------------------------------------------
// Kernel 2: partial channel mean/max of x*ca. grid (2, 8, 32) = 512 blocks.
// ---------------------------------------------------------------------------
__global__ __launch_bounds__(256, 2) void k_chan_pool(const float* __restrict__ x) {
    const int chunk = blockIdx.x, cg = blockIdx.y, b = blockIdx.z;
    const int t = threadIdx.x;
    __shared__ float sca[C_];
    sca[t] = g_ca[b * C_ + t];
    __syncthreads();

    const int f8 = chunk * 256 + t;
    if (f8 >= HW8_) return;
    const float* __restrict__ xb =
        x + (size_t)b * C_ * HW_ + (size_t)cg * CG_ * HW_ + (size_t)f8 * 8;
    const float* __restrict__ scg = sca + cg * CG_;
    float4 slo = make_float4(0.f, 0.f, 0.f, 0.f), shi = slo;
    float4 mlo = make_float4(-INFINITY, -INFINITY, -INFINITY, -INFINITY), mhi = mlo;
    #pragma unroll
    for (int batch = 0; batch < 4; batch++) {
        float4 lo[8], hi[8];
        #pragma unroll
        for (int j = 0; j < 8; j++)
            ldg_evl8(xb + (size_t)(batch * 8 + j) * HW_, lo[j], hi[j]);
        #pragma unroll
        for (int j = 0; j < 8; j++) {
            const float a = scg[batch * 8 + j];
            float v0 = lo[j].x * a, v1 = lo[j].y * a, v2 = lo[j].z * a, v3 = lo[j].w * a;
            float v4 = hi[j].x * a, v5 = hi[j].y * a, v6 = hi[j].z * a, v7 = hi[j].w * a;
            slo.x += v0; slo.y += v1; slo.z += v2; slo.w += v3;
            shi.x += v4; shi.y += v5; shi.z += v6; shi.w += v7;
            mlo.x = fmaxf(mlo.x, v0); mlo.y = fmaxf(mlo.y, v1);
            mlo.z = fmaxf(mlo.z, v2); mlo.w = fmaxf(mlo.w, v3);
            mhi.x = fmaxf(mhi.x, v4); mhi.y = fmaxf(mhi.y, v5);
            mhi.z = fmaxf(mhi.z, v6); mhi.w = fmaxf(mhi.w, v7);
        }
    }
    const size_t base = ((size_t)b * NCG_ + cg) * HW_;
    stg_evl8(g_ps + base + (size_t)f8 * 8, slo, shi);
    stg_evl8(g_pm + base + (size_t)f8 * 8, mlo, mhi);
}

// ---------------------------------------------------------------------------
// Kernel 3: merge partials + 7x7 conv + sigmoid -> g_sa.
// TR=8: grid (7, 32) = 224 blocks x 256 threads.
// ---------------------------------------------------------------------------
#define TR 8
#define HR (TR + 6)                // 14 halo rows
#define HF8 (HR * W_ / 8)          // 98 float8 in halo tile

__global__ __launch_bounds__(256) void k_sa(const float* __restrict__ wsp) {
    const int b  = blockIdx.y;
    const int h0 = blockIdx.x * TR;
    const int t  = threadIdx.x;

    __shared__ float sw[98];
    __shared__ __align__(32) float spa[HR * W_];
    __shared__ __align__(32) float spm[HR * W_];

    if (t >= 128 && t < 226) sw[t - 128] = wsp[t - 128];

    if (t < HF8) {
        const int r  = t / W8_;
        const int c8 = t - r * W8_;
        const int hh = h0 - 3 + r;
        float4 slo = make_float4(0.f, 0.f, 0.f, 0.f), shi = slo;
        float4 mlo = slo, mhi = slo;
        if (hh >= 0 && hh < H_) {
            const size_t p = (size_t)(hh * W8_ + c8) * 8;
            const float* __restrict__ ps = g_ps + (size_t)b * NCG_ * HW_ + p;
            const float* __restrict__ pm = g_pm + (size_t)b * NCG_ * HW_ + p;
            {
                float4 lo[NCG_], hi[NCG_];
                #pragma unroll
                for (int g = 0; g < NCG_; g++) ldg8(ps + (size_t)g * HW_, lo[g], hi[g]);
                slo = lo[0]; shi = hi[0];
                #pragma unroll
                for (int g = 1; g < NCG_; g++) {
                    slo.x += lo[g].x; slo.y += lo[g].y; slo.z += lo[g].z; slo.w += lo[g].w;
                    shi.x += hi[g].x; shi.y += hi[g].y; shi.z += hi[g].z; shi.w += hi[g].w;
                }
                const float inv = 1.0f / C_;
                slo.x *= inv; slo.y *= inv; slo.z *= inv; slo.w *= inv;
                shi.x *= inv; shi.y *= inv; shi.z *= inv; shi.w *= inv;
            }
            {
                float4 lo[NCG_], hi[NCG_];
                #pragma unroll
                for (int g = 0; g < NCG_; g++) ldg8(pm + (size_t)g * HW_, lo[g], hi[g]);
                mlo = lo[0]; mhi = hi[0];
                #pragma unroll
                for (int g = 1; g < NCG_; g++) {
                    mlo.x = fmaxf(mlo.x, lo[g].x); mlo.y = fmaxf(mlo.y, lo[g].y);
                    mlo.z = fmaxf(mlo.z, lo[g].z); mlo.w = fmaxf(mlo.w, lo[g].w);
                    mhi.x = fmaxf(mhi.x, hi[g].x); mhi.y = fmaxf(mhi.y, hi[g].y);
                    mhi.z = fmaxf(mhi.z, hi[g].z); mhi.w = fmaxf(mhi.w, hi[g].w);
                }
            }
        }
        ((float4*)spa)[t * 2]     = slo;
        ((float4*)spa)[t * 2 + 1] = shi;
        ((float4*)spm)[t * 2]     = mlo;
        ((float4*)spm)[t * 2 + 1] = mhi;
    }
    __syncthreads();

    for (int p = t; p < TR * W_; p += 256) {
        const int hr = p / W_;
        const int wd = p - hr * W_;
        const int h  = h0 + hr;
        float acc = 0.f;
        #pragma unroll
        for (int kh = 0; kh < 7; kh++) {
            const int hh = h + kh - 3;
            if (hh < 0 || hh >= H_) continue;
            const int sr = hh - (h0 - 3);
            #pragma unroll
            for (int kw = 0; kw < 7; kw++) {
                const int ww = wd + kw - 3;
                if (ww < 0 || ww >= W_) continue;
                acc = fmaf(sw[kh * 7 + kw],      spa[sr * W_ + ww], acc);
                acc = fmaf(sw[49 + kh * 7 + kw], spm[sr * W_ + ww], acc);
            }
        }
        g_sa[b * HW_ + h * W_ + wd] = 1.0f / (1.0f + __expf(-acc));
    }
}

// ---------------------------------------------------------------------------
// Kernel 4: out = x * (1 + ca*sa). 4 f8 per thread. PDL: x loads are issued
// BEFORE cudaGridDependencySynchronize(); ca/sa reads after. Launched with
// programmatic stream serialization so its x streaming overlaps k_sa.
// ---------------------------------------------------------------------------
__global__ __launch_bounds__(256) void k_final(const float* __restrict__ x,
                                               float* __restrict__ out) {
    const int g = blockIdx.x * 256 + threadIdx.x;
    const int plane = g / QF8_;
    const int r = g - plane * QF8_;
    const int b = plane >> 8;
    const float*  __restrict__ xs = x + (size_t)plane * HW_ + (size_t)r * 8;

    // Independent prologue: stream x (bulk of this kernel's traffic).
    float4 vlo[4], vhi[4];
    #pragma unroll
    for (int j = 0; j < 4; j++)
        ldg_evf8(xs + (size_t)j * QF8_ * 8, vlo[j], vhi[j]);

    // Wait for k_sa's g_sa/g_ca to be complete & visible.
    cudaGridDependencySynchronize();

    const float ca = __ldg(&g_ca[plane]);
    const float4* __restrict__ ss = (const float4*)(g_sa + (size_t)b * HW_) + r * 2;
    float4*       __restrict__ os = (float4*)(out + (size_t)plane * HW_) + r * 2;
    float4 slo[4], shi[4];
    #pragma unroll
    for (int j = 0; j < 4; j++) {
        slo[j] = __ldg(ss + j * QF8_ * 2);
        shi[j] = __ldg(ss + j * QF8_ * 2 + 1);
    }
    #pragma unroll
    for (int j = 0; j < 4; j++) {
        float4 o1, o2;
        o1.x = vlo[j].x * fmaf(ca, slo[j].x, 1.0f);
        o1.y = vlo[j].y * fmaf(ca, slo[j].y, 1.0f);
        o1.z = vlo[j].z * fmaf(ca, slo[j].z, 1.0f);
        o1.w = vlo[j].w * fmaf(ca, slo[j].w, 1.0f);
        o2.x = vhi[j].x * fmaf(ca, shi[j].x, 1.0f);
        o2.y = vhi[j].y * fmaf(ca, shi[j].y, 1.0f);
        o2.z = vhi[j].z * fmaf(ca, shi[j].z, 1.0f);
        o2.w = vhi[j].w * fmaf(ca, shi[j].w, 1.0f);
        os[j * QF8_ * 2]     = o1;
        os[j * QF8_ * 2 + 1] = o2;
    }
}

// ---------------------------------------------------------------------------
extern "C" void kernel_launch(void* const* d_in, const int* in_sizes, int n_in,
                              void* d_out, int out_size) {
    const float* x   = (const float*)d_in[0];
    const float* w1  = (const float*)d_in[1];
    const float* w2  = (const float*)d_in[2];
    const float* wsp = (const float*)d_in[3];
    float* out = (float*)d_out;

    k_spatial_pool<<<1024, 256>>>(x);
    k_mlp<<<B_, 256>>>(w1, w2);
    dim3 g2((HW8_ + 255) / 256, NCG_, B_);       // (2, 8, 32) = 512 blocks
    k_chan_pool<<<g2, 256>>>(x);
    dim3 g3(H_ / TR, B_);                        // (7, 32) = 224 blocks
    k_sa<<<g3, 256>>>(wsp);

    // k_final with programmatic dependent launch: overlap with k_sa.
    cudaLaunchConfig_t cfg = {};
    cfg.gridDim  = dim3((B_ * C_ * QF8_) / 256);  // 3136 blocks
    cfg.blockDim = dim3(256);
    cudaLaunchAttribute attrs[1];
    attrs[0].id = cudaLaunchAttributeProgrammaticStreamSerialization;
    attrs[0].val.programmaticStreamSerializationAllowed = 1;
    cfg.attrs = attrs;
    cfg.numAttrs = 1;
    cudaLaunchKernelEx(&cfg, k_final, x, out);
}